// round 12
// baseline (speedup 1.0000x reference)
#include <cuda_runtime.h>
#include <cuda_fp16.h>

#define HID     1024
#define TSTEPS  4096
#define NCTA    128
#define NTH     512   // 16 warps: warp w -> rows 2w, 2w+1 of all 3 big matrices

// SMEM: Whh1/Wih2/Whh2 fp16 (3*64KB) + Wih1 (4KB) + sH1f/sH2f fp32 (2*4KB) + gates (256B)
#define SMEM_BYTES (3*65536 + 4096 + 2*4096 + 256)

// tagged h words: (tag << 32) | fp32 bits
__device__ __align__(16) unsigned long long g_h1q[2][HID];
__device__ __align__(16) unsigned long long g_h2q[2][HID];
__device__ unsigned g_cnt = 0;
__device__ unsigned g_gen = 0;

__device__ __forceinline__ float warpsum(float v) {
#pragma unroll
    for (int s = 16; s; s >>= 1) v += __shfl_xor_sync(0xffffffffu, v, s);
    return v;
}

__device__ __forceinline__ void gridbar() {   // used ONCE, after init
    __syncthreads();
    if (threadIdx.x == 0) {
        __threadfence();
        unsigned g = *((volatile unsigned*)&g_gen);
        if (atomicAdd(&g_cnt, 1u) == NCTA - 1) {
            atomicExch(&g_cnt, 0u);
            __threadfence();
            atomicExch(&g_gen, g + 1u);
        } else {
            while (*((volatile unsigned*)&g_gen) == g) { }
        }
    }
    __syncthreads();
}

__device__ __forceinline__ float sigf(float x) {
    return __fdividef(1.0f, 1.0f + __expf(-x));
}
__device__ __forceinline__ float tanhfast(float x) {
    return 2.0f * __fdividef(1.0f, 1.0f + __expf(-2.0f * x)) - 1.0f;
}

__device__ __forceinline__ void unp8(uint4 u, float* f) {
    float2 t;
    t = __half22float2(*reinterpret_cast<__half2*>(&u.x)); f[0] = t.x; f[1] = t.y;
    t = __half22float2(*reinterpret_cast<__half2*>(&u.y)); f[2] = t.x; f[3] = t.y;
    t = __half22float2(*reinterpret_cast<__half2*>(&u.z)); f[4] = t.x; f[5] = t.y;
    t = __half22float2(*reinterpret_cast<__half2*>(&u.w)); f[6] = t.x; f[7] = t.y;
}

__device__ __forceinline__ void ldcg2q(const unsigned long long* p,
                                       unsigned long long& a, unsigned long long& b) {
    asm volatile("ld.global.cg.v2.u64 {%0,%1}, [%2];"
                 : "=l"(a), "=l"(b) : "l"(p));
}

// poll own 2+2 words of h1/h2 until tags match, then stage fp32 pair into smem
__device__ __forceinline__ void poll_stage(const unsigned long long* p1w,
                                           const unsigned long long* p2w,
                                           unsigned tg, float* sH1f, float* sH2f,
                                           int tid) {
    unsigned long long a0, a1, b0, b1;
    bool oka = false, okb = false;
    do {
        if (!oka) { ldcg2q(p1w, a0, a1);
                    oka = ((unsigned)(a0 >> 32) == tg) & ((unsigned)(a1 >> 32) == tg); }
        if (!okb) { ldcg2q(p2w, b0, b1);
                    okb = ((unsigned)(b0 >> 32) == tg) & ((unsigned)(b1 >> 32) == tg); }
    } while (!(oka && okb));
    ((float2*)sH1f)[tid] = make_float2(__uint_as_float((unsigned)a0),
                                       __uint_as_float((unsigned)a1));
    ((float2*)sH2f)[tid] = make_float2(__uint_as_float((unsigned)b0),
                                       __uint_as_float((unsigned)b1));
}

__device__ __forceinline__ void ld8f(const float* s, int k, float* f) {
    float4 a = ((const float4*)s)[2 * k];
    float4 b = ((const float4*)s)[2 * k + 1];
    f[0] = a.x; f[1] = a.y; f[2] = a.z; f[3] = a.w;
    f[4] = b.x; f[5] = b.y; f[6] = b.z; f[7] = b.w;
}

__global__ void __launch_bounds__(NTH, 1)
lstm_persistent(const float* __restrict__ x,
                const float* __restrict__ Wih1, const float* __restrict__ Whh1,
                const float* __restrict__ bih1, const float* __restrict__ bhh1,
                const float* __restrict__ Wih2, const float* __restrict__ Whh2,
                const float* __restrict__ bih2, const float* __restrict__ bhh2,
                const float* __restrict__ Wout, const float* __restrict__ bout,
                float* __restrict__ out)
{
    extern __shared__ unsigned char sm[];
    __half* sWhh1 = (__half*)sm;                 // [32][1024]
    __half* sWih2 = sWhh1 + 32 * HID;
    __half* sWhh2 = sWih2 + 32 * HID;
    __half* sWih1 = sWhh2 + 32 * HID;            // [32][64]
    float*  sH1f  = (float*)(sWih1 + 32 * 64);   // h1(t)   fp32
    float*  sH2f  = sH1f + HID;                  // h2(t-1) fp32
    float*  sG1   = sH2f + HID;                  // 32 gate-row sums, layer1
    float*  sG2   = sG1 + 32;                    // 32 gate-row sums, layer2

    const int tid  = threadIdx.x;
    const int w    = tid >> 5;
    const int lane = tid & 31;
    const int b    = blockIdx.x;
    const int r0   = 2 * w;
    const int r1   = 2 * w + 1;

    // ---- preload: 3 big mats -> fp16 SMEM ----
    {
        const float* srcs[3] = { Whh1, Wih2, Whh2 };
        __half* dsts[3] = { sWhh1, sWih2, sWhh2 };
        for (int rr = w; rr < 96; rr += 16) {
            int m = rr >> 5, r = rr & 31;
            int g = r & 3, jg = 8 * b + (r >> 2);
            const float4* src = (const float4*)(srcs[m] + ((size_t)g * HID + jg) * HID);
            uint4* dst = (uint4*)(dsts[m] + r * HID);
#pragma unroll
            for (int i = 0; i < 4; ++i) {
                int k = lane + 32 * i;
                float4 a  = __ldg(src + 2 * k);
                float4 bb = __ldg(src + 2 * k + 1);
                uint4 u;
                ((__half2*)&u)[0] = __floats2half2_rn(a.x, a.y);
                ((__half2*)&u)[1] = __floats2half2_rn(a.z, a.w);
                ((__half2*)&u)[2] = __floats2half2_rn(bb.x, bb.y);
                ((__half2*)&u)[3] = __floats2half2_rn(bb.z, bb.w);
                dst[k] = u;
            }
        }
    }
    // ---- preload Wih1 rows r0,r1 ----
#pragma unroll
    for (int rl = 0; rl < 2; ++rl) {
        int r = 2 * w + rl;
        int g = r & 3, jg = 8 * b + (r >> 2);
        if (lane < 16) {
            float4 v = __ldg((const float4*)(Wih1 + ((size_t)g * HID + jg) * 64) + lane);
            __half2* d = (__half2*)(sWih1 + r * 64) + 2 * lane;
            d[0] = __floats2half2_rn(v.x, v.y);
            d[1] = __floats2half2_rn(v.z, v.w);
        }
    }

    // ---- clear stale tags (both parities), then seed h2(-1)=0 with tag 1 ----
    if (tid < 8) {
        int jg = 8 * b + tid;
        __stcg(&g_h1q[0][jg], 0ull);
        __stcg(&g_h1q[1][jg], 0ull);
        __stcg(&g_h2q[0][jg], 0ull);
        __stcg(&g_h2q[1][jg], (1ull << 32));   // tag 1, value fp32(0)
    }

    // ---- finisher role: lane0 of warp w finishes (layer fl, hidden fj) ----
    const int fl = w >> 3, fj = w & 7, fjg = 8 * b + fj;
    float bsum[4] = {0.f, 0.f, 0.f, 0.f};
    if (lane == 0) {
        const float* bi = fl ? bih2 : bih1;
        const float* bh = fl ? bhh2 : bhh1;
#pragma unroll
        for (int g = 0; g < 4; ++g)
            bsum[g] = __ldg(bi + g * HID + fjg) + __ldg(bh + g * HID + fjg);
    }
    float cstate = 0.0f;

    // ---- rotating output-projection duty: warp 15 of CTA ((t-1)&127) ----
    float bo0 = 0.f, bo1 = 0.f;
    if (w == 15) { bo0 = __ldg(bout); bo1 = __ldg(bout + 1); }

    gridbar();   // stale tags cleared everywhere before anyone publishes/polls

    // ---- prologue: h1(0) = gates(Wih1 @ x(0) + biases); publish tag 1 ----
    {
        float2 xv = __ldg((const float2*)x + lane);
        float2 w0 = __half22float2(((const __half2*)(sWih1 + r0 * 64))[lane]);
        float2 w1 = __half22float2(((const __half2*)(sWih1 + r1 * 64))[lane]);
        float a0 = warpsum(fmaf(w0.x, xv.x, w0.y * xv.y));
        float a1 = warpsum(fmaf(w1.x, xv.x, w1.y * xv.y));
        if (lane == 0) { sG1[r0] = a0; sG1[r1] = a1; }
        __syncthreads();
        if (lane == 0 && fl == 0) {
            float gi = sG1[fj * 4 + 0] + bsum[0];
            float gg = sG1[fj * 4 + 2] + bsum[2];
            float go = sG1[fj * 4 + 3] + bsum[3];
            cstate = sigf(gi) * tanhfast(gg);
            float h = sigf(go) * tanhfast(cstate);
            unsigned long long word = (1ull << 32)
                                    | (unsigned long long)__float_as_uint(h);
            __stcg(&g_h1q[0][fjg], word);
        }
        __syncthreads();   // finisher reads of sG done before t=0 writes it
    }

    // poll pointers per parity (this thread's 2 words of each array)
    const unsigned long long* h1p[2] = { &g_h1q[0][2 * tid], &g_h1q[1][2 * tid] };
    const unsigned long long* h2p[2] = { &g_h2q[0][2 * tid], &g_h2q[1][2 * tid] };

    // ==== main loop: interval t consumes h1(t),h2(t-1); publishes h2(t),h1(t+1) ====
    for (int t = 0; t < TSTEPS; ++t) {
        const int p1 = t & 1;
        const int p2 = p1 ^ 1;
        const unsigned tg = (unsigned)(t + 1);

        // ---- data-carrying barrier: poll + stage in one pass ----
        poll_stage(h1p[p1], h2p[p2], tg, sH1f, sH2f, tid);
        __syncthreads();

        // ---- rotating out duty: out[t-1] = Wout @ h2(t-1) from staged sH2f ----
        if (w == 15 && t > 0 && b == ((t - 1) & 127)) {
            float a0 = 0.f, a1 = 0.f;
#pragma unroll
            for (int c = 0; c < 16; ++c) {
                int k2 = lane + 32 * c;
                float2 hv = ((const float2*)sH2f)[k2];
                float2 w0v = __ldg((const float2*)Wout + k2);
                float2 w1v = __ldg((const float2*)(Wout + HID) + k2);
                a0 = fmaf(w0v.x, hv.x, fmaf(w0v.y, hv.y, a0));
                a1 = fmaf(w1v.x, hv.x, fmaf(w1v.y, hv.y, a1));
            }
            a0 = warpsum(a0); a1 = warpsum(a1);
            if (lane == 0) {
                out[(t - 1) * 2]     = a0 + bo0;
                out[(t - 1) * 2 + 1] = a1 + bo1;
            }
        }

        // ---- dots: a1* = Whh1@h1(t) rows r0,r1 ; a2* = Wih2@h1(t)+Whh2@h2(t-1) ----
        float a1x = 0.f, a1y = 0.f, a2x = 0.f, a2y = 0.f;
        const uint4* W11a = (const uint4*)(sWhh1 + r0 * HID);
        const uint4* W11b = (const uint4*)(sWhh1 + r1 * HID);
        const uint4* Wi2a = (const uint4*)(sWih2 + r0 * HID);
        const uint4* Wi2b = (const uint4*)(sWih2 + r1 * HID);
        const uint4* Wh2a = (const uint4*)(sWhh2 + r0 * HID);
        const uint4* Wh2b = (const uint4*)(sWhh2 + r1 * HID);
#pragma unroll
        for (int c = 0; c < 4; ++c) {
            int k = lane + 32 * c;
            float h1f[8], h2f[8], wf[8];
            ld8f(sH1f, k, h1f);
            ld8f(sH2f, k, h2f);
            unp8(W11a[k], wf);
#pragma unroll
            for (int e = 0; e < 8; ++e) a1x = fmaf(wf[e], h1f[e], a1x);
            unp8(W11b[k], wf);
#pragma unroll
            for (int e = 0; e < 8; ++e) a1y = fmaf(wf[e], h1f[e], a1y);
            unp8(Wi2a[k], wf);
#pragma unroll
            for (int e = 0; e < 8; ++e) a2x = fmaf(wf[e], h1f[e], a2x);
            unp8(Wi2b[k], wf);
#pragma unroll
            for (int e = 0; e < 8; ++e) a2y = fmaf(wf[e], h1f[e], a2y);
            unp8(Wh2a[k], wf);
#pragma unroll
            for (int e = 0; e < 8; ++e) a2x = fmaf(wf[e], h2f[e], a2x);
            unp8(Wh2b[k], wf);
#pragma unroll
            for (int e = 0; e < 8; ++e) a2y = fmaf(wf[e], h2f[e], a2y);
        }
        // + Wih1 @ x(t+1) into layer-1 rows
        {
            float2 xv = make_float2(0.f, 0.f);
            if (t + 1 < TSTEPS)
                xv = __ldg((const float2*)(x + (size_t)(t + 1) * 64) + lane);
            float2 w0 = __half22float2(((const __half2*)(sWih1 + r0 * 64))[lane]);
            float2 w1 = __half22float2(((const __half2*)(sWih1 + r1 * 64))[lane]);
            a1x = fmaf(w0.x, xv.x, fmaf(w0.y, xv.y, a1x));
            a1y = fmaf(w1.x, xv.x, fmaf(w1.y, xv.y, a1y));
        }

        a1x = warpsum(a1x); a1y = warpsum(a1y);
        a2x = warpsum(a2x); a2y = warpsum(a2y);
        if (lane == 0) { sG1[r0] = a1x; sG1[r1] = a1y; sG2[r0] = a2x; sG2[r1] = a2y; }
        __syncthreads();

        // ---- finish: lane0 of warp w updates (fl,fj), publishes tagged fp32 ----
        if (lane == 0) {
            const float* sG = fl ? sG2 : sG1;
            float gi = sG[fj * 4 + 0] + bsum[0];
            float gf = sG[fj * 4 + 1] + bsum[1];
            float gg = sG[fj * 4 + 2] + bsum[2];
            float go = sG[fj * 4 + 3] + bsum[3];
            cstate = sigf(gf) * cstate + sigf(gi) * tanhfast(gg);
            float h = sigf(go) * tanhfast(cstate);
            unsigned long long word = ((unsigned long long)(t + 2) << 32)
                                    | (unsigned long long)__float_as_uint(h);
            if (fl == 0) __stcg(&g_h1q[p2][fjg], word);   // h1(t+1)
            else         __stcg(&g_h2q[p1][fjg], word);   // h2(t)
        }
        // no end-of-loop barrier: next interval's poll gates on all publishes
    }

    // ---- epilogue: out[T-1] from h2(T-1) (tag 4097, parity 1), CTA 127 warp 15 ----
    if (w == 15 && b == ((TSTEPS - 1) & 127)) {
        const unsigned tgf = (unsigned)(TSTEPS + 1);
        float a0 = 0.f, a1 = 0.f;
        const int base = 32 * lane;
#pragma unroll
        for (int i = 0; i < 16; ++i) {
            unsigned long long u0, u1;
            const unsigned long long* pp = &g_h2q[1][base + 2 * i];
            do { ldcg2q(pp, u0, u1); }
            while (((unsigned)(u0 >> 32) != tgf) || ((unsigned)(u1 >> 32) != tgf));
            float h0 = __uint_as_float((unsigned)u0);
            float h1v = __uint_as_float((unsigned)u1);
            float2 w0v = __ldg((const float2*)(Wout + base) + i);
            float2 w1v = __ldg((const float2*)(Wout + HID + base) + i);
            a0 = fmaf(w0v.x, h0, fmaf(w0v.y, h1v, a0));
            a1 = fmaf(w1v.x, h0, fmaf(w1v.y, h1v, a1));
        }
        a0 = warpsum(a0); a1 = warpsum(a1);
        if (lane == 0) {
            out[(TSTEPS - 1) * 2]     = a0 + bo0;
            out[(TSTEPS - 1) * 2 + 1] = a1 + bo1;
        }
    }
}

extern "C" void kernel_launch(void* const* d_in, const int* in_sizes, int n_in,
                              void* d_out, int out_size)
{
    const float* x    = (const float*)d_in[0];
    const float* Wih1 = (const float*)d_in[1];
    const float* Whh1 = (const float*)d_in[2];
    const float* bih1 = (const float*)d_in[3];
    const float* bhh1 = (const float*)d_in[4];
    const float* Wih2 = (const float*)d_in[5];
    const float* Whh2 = (const float*)d_in[6];
    const float* bih2 = (const float*)d_in[7];
    const float* bhh2 = (const float*)d_in[8];
    const float* Wout = (const float*)d_in[9];
    const float* bout = (const float*)d_in[10];
    float* out = (float*)d_out;

    cudaFuncSetAttribute(lstm_persistent,
                         cudaFuncAttributeMaxDynamicSharedMemorySize, SMEM_BYTES);

    lstm_persistent<<<NCTA, NTH, SMEM_BYTES>>>(x, Wih1, Whh1, bih1, bhh1,
                                               Wih2, Whh2, bih2, bhh2,
                                               Wout, bout, out);
}

// round 13
// speedup vs baseline: 1.1804x; 1.1804x over previous
#include <cuda_runtime.h>
#include <cuda_fp16.h>

#define HID     1024
#define TSTEPS  4096
#define NCTA    128
#define NTH     512   // 16 warps: warp w -> rows 2w, 2w+1 of all 3 big matrices

// SMEM: Whh1/Wih2/Whh2 fp16 (3*64KB) + Wih1 (4KB) + h stage 4*2KB + gates 256B
#define SMEM_BYTES (3*65536 + 4096 + 4*2048 + 256)

// tagged h words: (tag << 32) | fp32 bits
__device__ __align__(16) unsigned long long g_h1q[2][HID];
__device__ __align__(16) unsigned long long g_h2q[2][HID];
__device__ unsigned g_cnt = 0;
__device__ unsigned g_gen = 0;

__device__ __forceinline__ float warpsum(float v) {
#pragma unroll
    for (int s = 16; s; s >>= 1) v += __shfl_xor_sync(0xffffffffu, v, s);
    return v;
}

__device__ __forceinline__ void gridbar() {   // used ONCE, after init
    __syncthreads();
    if (threadIdx.x == 0) {
        __threadfence();
        unsigned g = *((volatile unsigned*)&g_gen);
        if (atomicAdd(&g_cnt, 1u) == NCTA - 1) {
            atomicExch(&g_cnt, 0u);
            __threadfence();
            atomicExch(&g_gen, g + 1u);
        } else {
            while (*((volatile unsigned*)&g_gen) == g) { }
        }
    }
    __syncthreads();
}

__device__ __forceinline__ float sigf(float x) {
    return __fdividef(1.0f, 1.0f + __expf(-x));
}
__device__ __forceinline__ float tanhfast(float x) {
    return 2.0f * __fdividef(1.0f, 1.0f + __expf(-2.0f * x)) - 1.0f;
}

__device__ __forceinline__ void unp8(uint4 u, float* f) {
    float2 t;
    t = __half22float2(*reinterpret_cast<__half2*>(&u.x)); f[0] = t.x; f[1] = t.y;
    t = __half22float2(*reinterpret_cast<__half2*>(&u.y)); f[2] = t.x; f[3] = t.y;
    t = __half22float2(*reinterpret_cast<__half2*>(&u.z)); f[4] = t.x; f[5] = t.y;
    t = __half22float2(*reinterpret_cast<__half2*>(&u.w)); f[6] = t.x; f[7] = t.y;
}

__device__ __forceinline__ void ldcg2q(const unsigned long long* p,
                                       unsigned long long& a, unsigned long long& b) {
    asm volatile("ld.global.cg.v2.u64 {%0,%1}, [%2];"
                 : "=l"(a), "=l"(b) : "l"(p));
}

// poll own 2+2 words of h1/h2 until tags match, then store fp32 pairs to
// precomputed conflict-free A/B slots
__device__ __forceinline__ void poll_stage(const unsigned long long* p1w,
                                           const unsigned long long* p2w,
                                           unsigned tg, float2* d1, float2* d2) {
    unsigned long long a0, a1, b0, b1;
    bool oka = false, okb = false;
    do {
        if (!oka) { ldcg2q(p1w, a0, a1);
                    oka = ((unsigned)(a0 >> 32) == tg) & ((unsigned)(a1 >> 32) == tg); }
        if (!okb) { ldcg2q(p2w, b0, b1);
                    okb = ((unsigned)(b0 >> 32) == tg) & ((unsigned)(b1 >> 32) == tg); }
    } while (!(oka && okb));
    *d1 = make_float2(__uint_as_float((unsigned)a0), __uint_as_float((unsigned)a1));
    *d2 = make_float2(__uint_as_float((unsigned)b0), __uint_as_float((unsigned)b1));
}

// reconstruct h[8k..8k+8) from split A/B arrays (conflict-free LDS.128)
__device__ __forceinline__ void ld8f2(const float* A, const float* B, int k, float* f) {
    float4 a = ((const float4*)A)[k];
    float4 b = ((const float4*)B)[k];
    f[0] = a.x; f[1] = a.y; f[2] = a.z; f[3] = a.w;
    f[4] = b.x; f[5] = b.y; f[6] = b.z; f[7] = b.w;
}

__global__ void __launch_bounds__(NTH, 1)
lstm_persistent(const float* __restrict__ x,
                const float* __restrict__ Wih1, const float* __restrict__ Whh1,
                const float* __restrict__ bih1, const float* __restrict__ bhh1,
                const float* __restrict__ Wih2, const float* __restrict__ Whh2,
                const float* __restrict__ bih2, const float* __restrict__ bhh2,
                const float* __restrict__ Wout, const float* __restrict__ bout,
                float* __restrict__ out)
{
    extern __shared__ unsigned char sm[];
    __half* sWhh1 = (__half*)sm;                 // [32][1024]
    __half* sWih2 = sWhh1 + 32 * HID;
    __half* sWhh2 = sWih2 + 32 * HID;
    __half* sWih1 = sWhh2 + 32 * HID;            // [32][64]
    float*  sH1A  = (float*)(sWih1 + 32 * 64);   // h1(t) elements idx%8<4 (512 f)
    float*  sH1B  = sH1A + 512;                  // h1(t) elements idx%8>=4
    float*  sH2A  = sH1B + 512;                  // h2(t-1) split likewise
    float*  sH2B  = sH2A + 512;
    float*  sG1   = sH2B + 512;                  // 32 gate-row sums, layer1
    float*  sG2   = sG1 + 32;                    // 32 gate-row sums, layer2

    const int tid  = threadIdx.x;
    const int w    = tid >> 5;
    const int lane = tid & 31;
    const int b    = blockIdx.x;
    const int r0   = 2 * w;
    const int r1   = 2 * w + 1;

    // conflict-free staging slots for this thread's polled float2s
    const int mgrp = tid >> 2, msub = tid & 3;
    const int slot = 2 * mgrp + (msub & 1);
    float2* d1 = (float2*)((msub < 2) ? sH1A : sH1B) + slot;
    float2* d2 = (float2*)((msub < 2) ? sH2A : sH2B) + slot;

    // ---- preload: 3 big mats -> fp16 SMEM ----
    {
        const float* srcs[3] = { Whh1, Wih2, Whh2 };
        __half* dsts[3] = { sWhh1, sWih2, sWhh2 };
        for (int rr = w; rr < 96; rr += 16) {
            int m = rr >> 5, r = rr & 31;
            int g = r & 3, jg = 8 * b + (r >> 2);
            const float4* src = (const float4*)(srcs[m] + ((size_t)g * HID + jg) * HID);
            uint4* dst = (uint4*)(dsts[m] + r * HID);
#pragma unroll
            for (int i = 0; i < 4; ++i) {
                int k = lane + 32 * i;
                float4 a  = __ldg(src + 2 * k);
                float4 bb = __ldg(src + 2 * k + 1);
                uint4 u;
                ((__half2*)&u)[0] = __floats2half2_rn(a.x, a.y);
                ((__half2*)&u)[1] = __floats2half2_rn(a.z, a.w);
                ((__half2*)&u)[2] = __floats2half2_rn(bb.x, bb.y);
                ((__half2*)&u)[3] = __floats2half2_rn(bb.z, bb.w);
                dst[k] = u;
            }
        }
    }
    // ---- preload Wih1 rows r0,r1 ----
#pragma unroll
    for (int rl = 0; rl < 2; ++rl) {
        int r = 2 * w + rl;
        int g = r & 3, jg = 8 * b + (r >> 2);
        if (lane < 16) {
            float4 v = __ldg((const float4*)(Wih1 + ((size_t)g * HID + jg) * 64) + lane);
            __half2* d = (__half2*)(sWih1 + r * 64) + 2 * lane;
            d[0] = __floats2half2_rn(v.x, v.y);
            d[1] = __floats2half2_rn(v.z, v.w);
        }
    }

    // ---- clear stale tags (both parities), then seed h2(-1)=0 with tag 1 ----
    if (tid < 8) {
        int jg = 8 * b + tid;
        __stcg(&g_h1q[0][jg], 0ull);
        __stcg(&g_h1q[1][jg], 0ull);
        __stcg(&g_h2q[0][jg], 0ull);
        __stcg(&g_h2q[1][jg], (1ull << 32));   // tag 1, value fp32(0)
    }

    // ---- finisher role: lane0 of warp w finishes (layer fl, hidden fj) ----
    const int fl = w >> 3, fj = w & 7, fjg = 8 * b + fj;
    float bsum[4] = {0.f, 0.f, 0.f, 0.f};
    if (lane == 0) {
        const float* bi = fl ? bih2 : bih1;
        const float* bh = fl ? bhh2 : bhh1;
#pragma unroll
        for (int g = 0; g < 4; ++g)
            bsum[g] = __ldg(bi + g * HID + fjg) + __ldg(bh + g * HID + fjg);
    }
    float cstate = 0.0f;

    // ---- output-projection role (warp 15 of CTA 1 -> col0, CTA 65 -> col1) ----
    const bool outcta = (b == 1 || b == 65);
    const bool outw = (w == 15) && outcta;
    const int  oi   = (b == 65) ? 1 : 0;
    float bo = 0.0f;
    if (outw && lane == 0) bo = __ldg(bout + oi);
    const float4* worow = (const float4*)(Wout + oi * HID);

    gridbar();   // stale tags cleared everywhere before anyone publishes/polls

    // ---- prologue: h1(0) = gates(Wih1 @ x(0) + biases); publish tag 1 ----
    {
        float2 xv = __ldg((const float2*)x + lane);
        float2 w0 = __half22float2(((const __half2*)(sWih1 + r0 * 64))[lane]);
        float2 w1 = __half22float2(((const __half2*)(sWih1 + r1 * 64))[lane]);
        float a0 = warpsum(fmaf(w0.x, xv.x, w0.y * xv.y));
        float a1 = warpsum(fmaf(w1.x, xv.x, w1.y * xv.y));
        if (lane == 0) { sG1[r0] = a0; sG1[r1] = a1; }
        __syncthreads();
        if (lane == 0 && fl == 0) {
            float gi = sG1[fj * 4 + 0] + bsum[0];
            float gg = sG1[fj * 4 + 2] + bsum[2];
            float go = sG1[fj * 4 + 3] + bsum[3];
            cstate = sigf(gi) * tanhfast(gg);
            float h = sigf(go) * tanhfast(cstate);
            unsigned long long word = (1ull << 32)
                                    | (unsigned long long)__float_as_uint(h);
            __stcg(&g_h1q[0][fjg], word);
        }
        __syncthreads();   // finisher reads of sG done before t=0 writes it
    }

    // poll pointers per parity (this thread's 2 words of each array)
    const unsigned long long* h1p[2] = { &g_h1q[0][2 * tid], &g_h1q[1][2 * tid] };
    const unsigned long long* h2p[2] = { &g_h2q[0][2 * tid], &g_h2q[1][2 * tid] };

    // ==== main loop: interval t consumes h1(t),h2(t-1); publishes h2(t),h1(t+1) ====
    for (int t = 0; t < TSTEPS; ++t) {
        const int p1 = t & 1;
        const int p2 = p1 ^ 1;
        const unsigned tg = (unsigned)(t + 1);

        // ---- data-carrying barrier: poll + stage in one pass ----
        poll_stage(h1p[p1], h2p[p2], tg, d1, d2);
        __syncthreads();

        // out[t-1] = Wout @ h2(t-1) (same FMA order as r5)
        if (outw && t > 0) {
            float a = 0.f;
#pragma unroll
            for (int c = 0; c < 4; ++c) {
                int k = lane + 32 * c;
                float hf[8]; ld8f2(sH2A, sH2B, k, hf);
                float4 wa = __ldg(worow + 2 * k);
                float4 wb = __ldg(worow + 2 * k + 1);
                a = fmaf(wa.x, hf[0], fmaf(wa.y, hf[1], fmaf(wa.z, hf[2], fmaf(wa.w, hf[3], a))));
                a = fmaf(wb.x, hf[4], fmaf(wb.y, hf[5], fmaf(wb.z, hf[6], fmaf(wb.w, hf[7], a))));
            }
            a = warpsum(a);
            if (lane == 0) out[(t - 1) * 2 + oi] = a + bo;
        }

        // ---- dots: a1* = Whh1@h1(t) rows r0,r1 ; a2* = Wih2@h1(t)+Whh2@h2(t-1) ----
        float a1x = 0.f, a1y = 0.f, a2x = 0.f, a2y = 0.f;
        const uint4* W11a = (const uint4*)(sWhh1 + r0 * HID);
        const uint4* W11b = (const uint4*)(sWhh1 + r1 * HID);
        const uint4* Wi2a = (const uint4*)(sWih2 + r0 * HID);
        const uint4* Wi2b = (const uint4*)(sWih2 + r1 * HID);
        const uint4* Wh2a = (const uint4*)(sWhh2 + r0 * HID);
        const uint4* Wh2b = (const uint4*)(sWhh2 + r1 * HID);
#pragma unroll
        for (int c = 0; c < 4; ++c) {
            int k = lane + 32 * c;
            float h1f[8], h2f[8], wf[8];
            ld8f2(sH1A, sH1B, k, h1f);
            ld8f2(sH2A, sH2B, k, h2f);
            unp8(W11a[k], wf);
#pragma unroll
            for (int e = 0; e < 8; ++e) a1x = fmaf(wf[e], h1f[e], a1x);
            unp8(W11b[k], wf);
#pragma unroll
            for (int e = 0; e < 8; ++e) a1y = fmaf(wf[e], h1f[e], a1y);
            unp8(Wi2a[k], wf);
#pragma unroll
            for (int e = 0; e < 8; ++e) a2x = fmaf(wf[e], h1f[e], a2x);
            unp8(Wi2b[k], wf);
#pragma unroll
            for (int e = 0; e < 8; ++e) a2y = fmaf(wf[e], h1f[e], a2y);
            unp8(Wh2a[k], wf);
#pragma unroll
            for (int e = 0; e < 8; ++e) a2x = fmaf(wf[e], h2f[e], a2x);
            unp8(Wh2b[k], wf);
#pragma unroll
            for (int e = 0; e < 8; ++e) a2y = fmaf(wf[e], h2f[e], a2y);
        }
        // + Wih1 @ x(t+1) into layer-1 rows
        {
            float2 xv = make_float2(0.f, 0.f);
            if (t + 1 < TSTEPS)
                xv = __ldg((const float2*)(x + (size_t)(t + 1) * 64) + lane);
            float2 w0 = __half22float2(((const __half2*)(sWih1 + r0 * 64))[lane]);
            float2 w1 = __half22float2(((const __half2*)(sWih1 + r1 * 64))[lane]);
            a1x = fmaf(w0.x, xv.x, fmaf(w0.y, xv.y, a1x));
            a1y = fmaf(w1.x, xv.x, fmaf(w1.y, xv.y, a1y));
        }

        a1x = warpsum(a1x); a1y = warpsum(a1y);
        a2x = warpsum(a2x); a2y = warpsum(a2y);
        if (lane == 0) { sG1[r0] = a1x; sG1[r1] = a1y; sG2[r0] = a2x; sG2[r1] = a2y; }
        __syncthreads();

        // ---- finish: lane0 of warp w updates (fl,fj), publishes tagged fp32 ----
        if (lane == 0) {
            const float* sG = fl ? sG2 : sG1;
            float gi = sG[fj * 4 + 0] + bsum[0];
            float gf = sG[fj * 4 + 1] + bsum[1];
            float gg = sG[fj * 4 + 2] + bsum[2];
            float go = sG[fj * 4 + 3] + bsum[3];
            cstate = sigf(gf) * cstate + sigf(gi) * tanhfast(gg);
            float h = sigf(go) * tanhfast(cstate);
            unsigned long long word = ((unsigned long long)(t + 2) << 32)
                                    | (unsigned long long)__float_as_uint(h);
            if (fl == 0) __stcg(&g_h1q[p2][fjg], word);   // h1(t+1)
            else         __stcg(&g_h2q[p1][fjg], word);   // h2(t)
        }
        // no end-of-loop barrier: next interval's poll gates on all publishes
    }

    // ---- epilogue: out[T-1] from h2(T-1) (tag 4097, parity 1) ----
    if (outcta) {
        {
            unsigned long long b0v, b1v;
            const unsigned tg = (unsigned)(TSTEPS + 1);
            bool ok = false;
            do { ldcg2q(h2p[1], b0v, b1v);
                 ok = ((unsigned)(b0v >> 32) == tg) & ((unsigned)(b1v >> 32) == tg);
            } while (!ok);
            *d2 = make_float2(__uint_as_float((unsigned)b0v),
                              __uint_as_float((unsigned)b1v));
        }
        __syncthreads();
        if (outw) {
            float a = 0.f;
#pragma unroll
            for (int c = 0; c < 4; ++c) {
                int k = lane + 32 * c;
                float hf[8]; ld8f2(sH2A, sH2B, k, hf);
                float4 wa = __ldg(worow + 2 * k);
                float4 wb = __ldg(worow + 2 * k + 1);
                a = fmaf(wa.x, hf[0], fmaf(wa.y, hf[1], fmaf(wa.z, hf[2], fmaf(wa.w, hf[3], a))));
                a = fmaf(wb.x, hf[4], fmaf(wb.y, hf[5], fmaf(wb.z, hf[6], fmaf(wb.w, hf[7], a))));
            }
            a = warpsum(a);
            if (lane == 0) out[(TSTEPS - 1) * 2 + oi] = a + bo;
        }
    }
}

extern "C" void kernel_launch(void* const* d_in, const int* in_sizes, int n_in,
                              void* d_out, int out_size)
{
    const float* x    = (const float*)d_in[0];
    const float* Wih1 = (const float*)d_in[1];
    const float* Whh1 = (const float*)d_in[2];
    const float* bih1 = (const float*)d_in[3];
    const float* bhh1 = (const float*)d_in[4];
    const float* Wih2 = (const float*)d_in[5];
    const float* Whh2 = (const float*)d_in[6];
    const float* bih2 = (const float*)d_in[7];
    const float* bhh2 = (const float*)d_in[8];
    const float* Wout = (const float*)d_in[9];
    const float* bout = (const float*)d_in[10];
    float* out = (float*)d_out;

    cudaFuncSetAttribute(lstm_persistent,
                         cudaFuncAttributeMaxDynamicSharedMemorySize, SMEM_BYTES);

    lstm_persistent<<<NCTA, NTH, SMEM_BYTES>>>(x, Wih1, Whh1, bih1, bhh1,
                                               Wih2, Whh2, bih2, bhh2,
                                               Wout, bout, out);
}

// round 15
// speedup vs baseline: 1.2650x; 1.0717x over previous
#include <cuda_runtime.h>
#include <cuda_fp16.h>

#define HID     1024
#define TSTEPS  4096
#define NCTA    128
#define NTH     512   // 16 warps: warp w -> rows 2w, 2w+1; pair (2j,2j+1) owns hidden j

// SMEM: Whh1/Wih2/Whh2 fp16 (3*64KB) + Wih1 (4KB) + h stage 4*2KB + sP 256B
#define SMEM_BYTES (3*65536 + 4096 + 4*2048 + 256)

// tagged h words: (tag << 32) | fp32 bits
__device__ __align__(16) unsigned long long g_h1q[2][HID];
__device__ __align__(16) unsigned long long g_h2q[2][HID];
__device__ unsigned g_cnt = 0;
__device__ unsigned g_gen = 0;

__device__ __forceinline__ float warpsum(float v) {
#pragma unroll
    for (int s = 16; s; s >>= 1) v += __shfl_xor_sync(0xffffffffu, v, s);
    return v;
}

__device__ __forceinline__ void gridbar() {   // used ONCE, after init
    __syncthreads();
    if (threadIdx.x == 0) {
        __threadfence();
        unsigned g = *((volatile unsigned*)&g_gen);
        if (atomicAdd(&g_cnt, 1u) == NCTA - 1) {
            atomicExch(&g_cnt, 0u);
            __threadfence();
            atomicExch(&g_gen, g + 1u);
        } else {
            while (*((volatile unsigned*)&g_gen) == g) { }
        }
    }
    __syncthreads();
}

__device__ __forceinline__ float sigf(float x) {
    return __fdividef(1.0f, 1.0f + __expf(-x));
}
__device__ __forceinline__ float tanhfast(float x) {
    return 2.0f * __fdividef(1.0f, 1.0f + __expf(-2.0f * x)) - 1.0f;
}

__device__ __forceinline__ void unp8(uint4 u, float* f) {
    float2 t;
    t = __half22float2(*reinterpret_cast<__half2*>(&u.x)); f[0] = t.x; f[1] = t.y;
    t = __half22float2(*reinterpret_cast<__half2*>(&u.y)); f[2] = t.x; f[3] = t.y;
    t = __half22float2(*reinterpret_cast<__half2*>(&u.z)); f[4] = t.x; f[5] = t.y;
    t = __half22float2(*reinterpret_cast<__half2*>(&u.w)); f[6] = t.x; f[7] = t.y;
}

__device__ __forceinline__ void ldcg2q(const unsigned long long* p,
                                       unsigned long long& a, unsigned long long& b) {
    asm volatile("ld.global.cg.v2.u64 {%0,%1}, [%2];"
                 : "=l"(a), "=l"(b) : "l"(p));
}

// fused poll: own 2+2 words of h1/h2 until tags match, then stage to A/B slots
__device__ __forceinline__ void poll_stage(const unsigned long long* p1w,
                                           const unsigned long long* p2w,
                                           unsigned tg, float2* d1, float2* d2) {
    unsigned long long a0, a1, b0, b1;
    bool oka = false, okb = false;
    do {
        if (!oka) { ldcg2q(p1w, a0, a1);
                    oka = ((unsigned)(a0 >> 32) == tg) & ((unsigned)(a1 >> 32) == tg); }
        if (!okb) { ldcg2q(p2w, b0, b1);
                    okb = ((unsigned)(b0 >> 32) == tg) & ((unsigned)(b1 >> 32) == tg); }
    } while (!(oka && okb));
    *d1 = make_float2(__uint_as_float((unsigned)a0), __uint_as_float((unsigned)a1));
    *d2 = make_float2(__uint_as_float((unsigned)b0), __uint_as_float((unsigned)b1));
}

// reconstruct h[8k..8k+8) from split A/B arrays (conflict-free LDS.128)
__device__ __forceinline__ void ld8f2(const float* A, const float* B, int k, float* f) {
    float4 a = ((const float4*)A)[k];
    float4 b = ((const float4*)B)[k];
    f[0] = a.x; f[1] = a.y; f[2] = a.z; f[3] = a.w;
    f[4] = b.x; f[5] = b.y; f[6] = b.z; f[7] = b.w;
}

__global__ void __launch_bounds__(NTH, 1)
lstm_persistent(const float* __restrict__ x,
                const float* __restrict__ Wih1, const float* __restrict__ Whh1,
                const float* __restrict__ bih1, const float* __restrict__ bhh1,
                const float* __restrict__ Wih2, const float* __restrict__ Whh2,
                const float* __restrict__ bih2, const float* __restrict__ bhh2,
                const float* __restrict__ Wout, const float* __restrict__ bout,
                float* __restrict__ out)
{
    extern __shared__ unsigned char sm[];
    __half* sWhh1 = (__half*)sm;                 // [32][1024]
    __half* sWih2 = sWhh1 + 32 * HID;
    __half* sWhh2 = sWih2 + 32 * HID;
    __half* sWih1 = sWhh2 + 32 * HID;            // [32][64]
    float*  sH1A  = (float*)(sWih1 + 32 * 64);   // h1(t) elements idx%8<4 (512 f)
    float*  sH1B  = sH1A + 512;                  // h1(t) elements idx%8>=4
    float*  sH2A  = sH1B + 512;                  // h2(t-1) split likewise
    float*  sH2B  = sH2A + 512;
    float*  sP    = sH2B + 512;                  // [8 hidden][8]: a1 g0..3, a2 g0..3

    const int tid  = threadIdx.x;
    const int w    = tid >> 5;
    const int lane = tid & 31;
    const int b    = blockIdx.x;
    const int r0   = 2 * w;
    const int r1   = 2 * w + 1;
    const int j    = w >> 1;        // hidden unit this warp-pair owns
    const int odd  = w & 1;         // 0: gates 0,1 + h1 cell; 1: gates 2,3 + h2 cell
    const int jg   = 8 * b + j;

    // conflict-free staging slots for this thread's polled float2s
    const int mgrp = tid >> 2, msub = tid & 3;
    const int slot = 2 * mgrp + (msub & 1);
    float2* d1 = (float2*)((msub < 2) ? sH1A : sH1B) + slot;
    float2* d2 = (float2*)((msub < 2) ? sH2A : sH2B) + slot;

    // ---- preload: 3 big mats -> fp16 SMEM ----
    {
        const float* srcs[3] = { Whh1, Wih2, Whh2 };
        __half* dsts[3] = { sWhh1, sWih2, sWhh2 };
        for (int rr = w; rr < 96; rr += 16) {
            int m = rr >> 5, r = rr & 31;
            int g = r & 3, jgr = 8 * b + (r >> 2);
            const float4* src = (const float4*)(srcs[m] + ((size_t)g * HID + jgr) * HID);
            uint4* dst = (uint4*)(dsts[m] + r * HID);
#pragma unroll
            for (int i = 0; i < 4; ++i) {
                int k = lane + 32 * i;
                float4 a  = __ldg(src + 2 * k);
                float4 bb = __ldg(src + 2 * k + 1);
                uint4 u;
                ((__half2*)&u)[0] = __floats2half2_rn(a.x, a.y);
                ((__half2*)&u)[1] = __floats2half2_rn(a.z, a.w);
                ((__half2*)&u)[2] = __floats2half2_rn(bb.x, bb.y);
                ((__half2*)&u)[3] = __floats2half2_rn(bb.z, bb.w);
                dst[k] = u;
            }
        }
    }
    // ---- preload Wih1 rows r0,r1 ----
#pragma unroll
    for (int rl = 0; rl < 2; ++rl) {
        int r = 2 * w + rl;
        int g = r & 3, jgr = 8 * b + (r >> 2);
        if (lane < 16) {
            float4 v = __ldg((const float4*)(Wih1 + ((size_t)g * HID + jgr) * 64) + lane);
            __half2* d = (__half2*)(sWih1 + r * 64) + 2 * lane;
            d[0] = __floats2half2_rn(v.x, v.y);
            d[1] = __floats2half2_rn(v.z, v.w);
        }
    }

    // ---- clear stale tags (both parities), then seed h2(-1)=0 with tag 1 ----
    if (tid < 8) {
        int j8 = 8 * b + tid;
        __stcg(&g_h1q[0][j8], 0ull);
        __stcg(&g_h1q[1][j8], 0ull);
        __stcg(&g_h2q[0][j8], 0ull);
        __stcg(&g_h2q[1][j8], (1ull << 32));   // tag 1, value fp32(0)
    }

    // ---- cell role: lane0 of even warp -> L1 cell of hidden j; odd -> L2 cell ----
    float bsum[4] = {0.f, 0.f, 0.f, 0.f};
    if (lane == 0) {
        const float* bi = odd ? bih2 : bih1;
        const float* bh = odd ? bhh2 : bhh1;
#pragma unroll
        for (int g = 0; g < 4; ++g)
            bsum[g] = __ldg(bi + g * HID + jg) + __ldg(bh + g * HID + jg);
    }
    float cstate = 0.0f;

    // ---- output-projection role (warp 15 of CTA 1 -> col0, CTA 65 -> col1) ----
    const bool outcta = (b == 1 || b == 65);
    const bool outw = (w == 15) && outcta;
    const int  oi   = (b == 65) ? 1 : 0;
    float bo = 0.0f;
    if (outw && lane == 0) bo = __ldg(bout + oi);
    const float4* worow = (const float4*)(Wout + oi * HID);

    gridbar();   // stale tags cleared everywhere before anyone publishes/polls

    // ---- prologue: h1(0) = gates(Wih1 @ x(0) + biases); publish tag 1 ----
    {
        float2 xv = __ldg((const float2*)x + lane);
        float2 w0 = __half22float2(((const __half2*)(sWih1 + r0 * 64))[lane]);
        float2 w1 = __half22float2(((const __half2*)(sWih1 + r1 * 64))[lane]);
        float a0 = warpsum(fmaf(w0.x, xv.x, w0.y * xv.y));
        float a1 = warpsum(fmaf(w1.x, xv.x, w1.y * xv.y));
        if (lane == 0) { sP[j * 8 + odd * 2] = a0; sP[j * 8 + odd * 2 + 1] = a1; }
        __syncthreads();
        if (lane == 0 && odd == 0) {
            float gi = sP[j * 8 + 0] + bsum[0];
            float gg = sP[j * 8 + 2] + bsum[2];
            float go = sP[j * 8 + 3] + bsum[3];
            cstate = sigf(gi) * tanhfast(gg);
            float h = sigf(go) * tanhfast(cstate);
            unsigned long long word = (1ull << 32)
                                    | (unsigned long long)__float_as_uint(h);
            __stcg(&g_h1q[0][jg], word);
        }
        __syncthreads();   // cell reads of sP done before t=0 writes it
    }

    // poll pointers per parity (this thread's 2 words of each array)
    const unsigned long long* h1p[2] = { &g_h1q[0][2 * tid], &g_h1q[1][2 * tid] };
    const unsigned long long* h2p[2] = { &g_h2q[0][2 * tid], &g_h2q[1][2 * tid] };

    // ==== main loop: interval t consumes h1(t),h2(t-1); publishes h2(t),h1(t+1) ====
    for (int t = 0; t < TSTEPS; ++t) {
        const int p1 = t & 1;
        const int p2 = p1 ^ 1;
        const unsigned tg = (unsigned)(t + 1);

        // ---- fused data-carrying barrier: poll BOTH arrays, stage in one pass ----
        poll_stage(h1p[p1], h2p[p2], tg, d1, d2);
        __syncthreads();

        // ---- dots: a1* = Whh1@h1(t) rows r0,r1 ; a2* = Wih2@h1(t)+Whh2@h2(t-1) ----
        float a1x = 0.f, a1y = 0.f, a2x = 0.f, a2y = 0.f;
        const uint4* W11a = (const uint4*)(sWhh1 + r0 * HID);
        const uint4* W11b = (const uint4*)(sWhh1 + r1 * HID);
        const uint4* Wi2a = (const uint4*)(sWih2 + r0 * HID);
        const uint4* Wi2b = (const uint4*)(sWih2 + r1 * HID);
        const uint4* Wh2a = (const uint4*)(sWhh2 + r0 * HID);
        const uint4* Wh2b = (const uint4*)(sWhh2 + r1 * HID);
#pragma unroll
        for (int c = 0; c < 4; ++c) {
            int k = lane + 32 * c;
            float h1f[8], h2f[8], wf[8];
            ld8f2(sH1A, sH1B, k, h1f);
            ld8f2(sH2A, sH2B, k, h2f);
            unp8(W11a[k], wf);
#pragma unroll
            for (int e = 0; e < 8; ++e) a1x = fmaf(wf[e], h1f[e], a1x);
            unp8(W11b[k], wf);
#pragma unroll
            for (int e = 0; e < 8; ++e) a1y = fmaf(wf[e], h1f[e], a1y);
            unp8(Wi2a[k], wf);
#pragma unroll
            for (int e = 0; e < 8; ++e) a2x = fmaf(wf[e], h1f[e], a2x);
            unp8(Wi2b[k], wf);
#pragma unroll
            for (int e = 0; e < 8; ++e) a2y = fmaf(wf[e], h1f[e], a2y);
            unp8(Wh2a[k], wf);
#pragma unroll
            for (int e = 0; e < 8; ++e) a2x = fmaf(wf[e], h2f[e], a2x);
            unp8(Wh2b[k], wf);
#pragma unroll
            for (int e = 0; e < 8; ++e) a2y = fmaf(wf[e], h2f[e], a2y);
        }
        // + Wih1 @ x(t+1) into layer-1 rows
        {
            float2 xv = make_float2(0.f, 0.f);
            if (t + 1 < TSTEPS)
                xv = __ldg((const float2*)(x + (size_t)(t + 1) * 64) + lane);
            float2 w0 = __half22float2(((const __half2*)(sWih1 + r0 * 64))[lane]);
            float2 w1 = __half22float2(((const __half2*)(sWih1 + r1 * 64))[lane]);
            a1x = fmaf(w0.x, xv.x, fmaf(w0.y, xv.y, a1x));
            a1y = fmaf(w1.x, xv.x, fmaf(w1.y, xv.y, a1y));
        }

        a1x = warpsum(a1x); a1y = warpsum(a1y);
        a2x = warpsum(a2x); a2y = warpsum(a2y);
        if (lane == 0) {
            sP[j * 8 + odd * 2]     = a1x;   // a1 gate (odd*2)
            sP[j * 8 + odd * 2 + 1] = a1y;   // a1 gate (odd*2+1)
            sP[j * 8 + 4 + odd * 2]     = a2x;
            sP[j * 8 + 4 + odd * 2 + 1] = a2y;
        }
        // group barrier: 4 warps (2 warp-pairs) converge, then cells publish early
        asm volatile("bar.sync %0, 128;" :: "r"(1 + (w >> 2)) : "memory");

        // ---- cells: even lane0 -> h1(t+1); odd lane0 -> h2(t); publish tagged ----
        if (lane == 0) {
            const float* g4 = sP + j * 8 + odd * 4;   // a1 block or a2 block
            float gi = g4[0] + bsum[0];
            float gf = g4[1] + bsum[1];
            float gg = g4[2] + bsum[2];
            float go = g4[3] + bsum[3];
            cstate = sigf(gf) * cstate + sigf(gi) * tanhfast(gg);
            float h = sigf(go) * tanhfast(cstate);
            unsigned long long word = ((unsigned long long)(t + 2) << 32)
                                    | (unsigned long long)__float_as_uint(h);
            if (odd == 0) __stcg(&g_h1q[p2][jg], word);   // h1(t+1)
            else          __stcg(&g_h2q[p1][jg], word);   // h2(t)
        }

        // ---- out duty (off the publish path): out[t-1] = Wout @ h2(t-1) ----
        if (outw && t > 0) {
            float a = 0.f;
#pragma unroll
            for (int c = 0; c < 4; ++c) {
                int k = lane + 32 * c;
                float hf[8]; ld8f2(sH2A, sH2B, k, hf);
                float4 wa = __ldg(worow + 2 * k);
                float4 wb = __ldg(worow + 2 * k + 1);
                a = fmaf(wa.x, hf[0], fmaf(wa.y, hf[1], fmaf(wa.z, hf[2], fmaf(wa.w, hf[3], a))));
                a = fmaf(wb.x, hf[4], fmaf(wb.y, hf[5], fmaf(wb.z, hf[6], fmaf(wb.w, hf[7], a))));
            }
            a = warpsum(a);
            if (lane == 0) out[(t - 1) * 2 + oi] = a + bo;
        }

        // trailing CTA sync: orders sH/sP reads before next interval's writes
        __syncthreads();
    }

    // ---- epilogue: out[T-1] from h2(T-1) (tag 4097, parity 1) ----
    if (outcta) {
        {
            unsigned long long b0v, b1v;
            const unsigned tgf = (unsigned)(TSTEPS + 1);
            bool ok = false;
            do { ldcg2q(h2p[1], b0v, b1v);
                 ok = ((unsigned)(b0v >> 32) == tgf) & ((unsigned)(b1v >> 32) == tgf);
            } while (!ok);
            *d2 = make_float2(__uint_as_float((unsigned)b0v),
                              __uint_as_float((unsigned)b1v));
        }
        __syncthreads();
        if (outw) {
            float a = 0.f;
#pragma unroll
            for (int c = 0; c < 4; ++c) {
                int k = lane + 32 * c;
                float hf[8]; ld8f2(sH2A, sH2B, k, hf);
                float4 wa = __ldg(worow + 2 * k);
                float4 wb = __ldg(worow + 2 * k + 1);
                a = fmaf(wa.x, hf[0], fmaf(wa.y, hf[1], fmaf(wa.z, hf[2], fmaf(wa.w, hf[3], a))));
                a = fmaf(wb.x, hf[4], fmaf(wb.y, hf[5], fmaf(wb.z, hf[6], fmaf(wb.w, hf[7], a))));
            }
            a = warpsum(a);
            if (lane == 0) out[(TSTEPS - 1) * 2 + oi] = a + bo;
        }
    }
}

extern "C" void kernel_launch(void* const* d_in, const int* in_sizes, int n_in,
                              void* d_out, int out_size)
{
    const float* x    = (const float*)d_in[0];
    const float* Wih1 = (const float*)d_in[1];
    const float* Whh1 = (const float*)d_in[2];
    const float* bih1 = (const float*)d_in[3];
    const float* bhh1 = (const float*)d_in[4];
    const float* Wih2 = (const float*)d_in[5];
    const float* Whh2 = (const float*)d_in[6];
    const float* bih2 = (const float*)d_in[7];
    const float* bhh2 = (const float*)d_in[8];
    const float* Wout = (const float*)d_in[9];
    const float* bout = (const float*)d_in[10];
    float* out = (float*)d_out;

    cudaFuncSetAttribute(lstm_persistent,
                         cudaFuncAttributeMaxDynamicSharedMemorySize, SMEM_BYTES);

    lstm_persistent<<<NCTA, NTH, SMEM_BYTES>>>(x, Wih1, Whh1, bih1, bhh1,
                                               Wih2, Whh2, bih2, bhh2,
                                               Wout, bout, out);
}